// round 9
// baseline (speedup 1.0000x reference)
#include <cuda_runtime.h>

#define N_RAYS   (1 << 20)
#define T_ITERS  4
#define DIM      64
#define IN_DIM   24
#define INF_F    1e9f
#define XST      260          // Xs row stride in floats
#define RAYS_PB  256
#define THREADS  256

typedef unsigned long long ull;

__device__ __forceinline__ ull pack2(float lo, float hi) {
    ull r; asm("mov.b64 %0, {%1, %2};" : "=l"(r) : "f"(lo), "f"(hi)); return r;
}
__device__ __forceinline__ void unpack2(ull v, float& lo, float& hi) {
    asm("mov.b64 {%0, %1}, %2;" : "=f"(lo), "=f"(hi) : "l"(v));
}
__device__ __forceinline__ void fma2(ull& d, ull a, ull b) {
    asm("fma.rn.f32x2 %0, %1, %2, %0;" : "+l"(d) : "l"(a), "l"(b));
}
__device__ __forceinline__ ull fma2v(ull a, ull b, ull c) {
    ull r; asm("fma.rn.f32x2 %0, %1, %2, %3;" : "=l"(r) : "l"(a), "l"(b), "l"(c)); return r;
}
__device__ __forceinline__ ull add2(ull a, ull b) {
    ull r; asm("add.rn.f32x2 %0, %1, %2;" : "=l"(r) : "l"(a), "l"(b)); return r;
}
__device__ __forceinline__ ull mul2(ull a, ull b) {
    ull r; asm("mul.rn.f32x2 %0, %1, %2;" : "=l"(r) : "l"(a), "l"(b)); return r;
}

struct SM {
    float  W0[IN_DIM][DIM];   // 6 KB
    float  Ws[2][DIM][DIM];   // 32 KB
    float  b0[DIM];
    float  bs[2][DIM];
    float  g[2][DIM];
    float  be[2][DIM];
    float2 head[DIM];         // {Wc, Wd}
    float  isc[3], off[3], bc, bd;
    float  Xs[DIM][XST];      // transposed activations: [feature][ray]
};

// 8 rays x 8 cols tile: acc[rr][c] covers cols [8j+2c, 8j+2c+1]
template<int K>
__device__ __forceinline__ void gemm_tile(const float* __restrict__ Xs,
                                          const float* __restrict__ W,
                                          const float* __restrict__ bias,
                                          int i, int j, ull (&acc)[8][4])
{
    const ull* bu = (const ull*)(bias + 8 * j);
    #pragma unroll
    for (int c = 0; c < 4; ++c) {
        const ull b2 = bu[c];
        #pragma unroll
        for (int rr = 0; rr < 8; ++rr) acc[rr][c] = b2;
    }
    const float* arow = Xs + 8 * i;
    const float* brow = W + 8 * j;
    #pragma unroll 4
    for (int k = 0; k < K; ++k) {
        const float4 a0 = *(const float4*)(arow);
        const float4 a1 = *(const float4*)(arow + 4);
        const ulonglong2 w0 = ((const ulonglong2*)brow)[0];
        const ulonglong2 w1 = ((const ulonglong2*)brow)[1];
        const ull b[4] = { w0.x, w0.y, w1.x, w1.y };
        const float av[8] = { a0.x, a0.y, a0.z, a0.w, a1.x, a1.y, a1.z, a1.w };
        #pragma unroll
        for (int rr = 0; rr < 8; ++rr) {
            const ull au = pack2(av[rr], av[rr]);
            #pragma unroll
            for (int c = 0; c < 4; ++c) fma2(acc[rr][c], au, b[c]);
        }
        arow += XST;
        brow += DIM;
    }
}

__global__ __launch_bounds__(THREADS) void nbvh_kernel(
    const float* __restrict__ orig, const float* __restrict__ vec,
    const unsigned int* __restrict__ masks,
    const float* __restrict__ t1, const float* __restrict__ t2,
    const float* __restrict__ mesh_min, const float* __restrict__ mesh_max,
    const float* __restrict__ W0, const float* __restrict__ b0,
    const float* __restrict__ ln_g, const float* __restrict__ ln_b,
    const float* __restrict__ Ws, const float* __restrict__ bs,
    const float* __restrict__ Wc, const float* __restrict__ bc,
    const float* __restrict__ Wd, const float* __restrict__ bd,
    float* __restrict__ out, int two_part)
{
    extern __shared__ SM sm[];
    SM& s = sm[0];
    const int tid = threadIdx.x;

    // ---- weight staging ----
    for (int x = tid; x < IN_DIM * DIM; x += THREADS) ((float*)s.W0)[x] = W0[x];
    for (int x = tid; x < 2 * DIM * DIM; x += THREADS) ((float*)s.Ws)[x] = Ws[x];
    if (tid < DIM) {
        s.b0[tid]   = b0[tid];
        s.head[tid] = make_float2(Wc[tid], Wd[tid]);
    }
    if (tid >= 64 && tid < 64 + 2 * DIM) {
        const int x = tid - 64;
        ((float*)s.bs)[x] = bs[x];
        ((float*)s.g)[x]  = ln_g[x];
        ((float*)s.be)[x] = ln_b[x];
    }
    if (tid >= 192 && tid < 195) {
        const int c = tid - 192;
        float mn = mesh_min[c], mx = mesh_max[c];
        float min_infl = mn - 0.5f * (mx - mn);
        float is = 1.0f / (2.0f * (mx - mn));
        s.isc[c] = is;
        s.off[c] = -min_infl * is;
    }
    if (tid == 195) { s.bc = bc[0]; s.bd = bd[0]; }
    __syncthreads();

    const int j = tid & 7;          // col group: cols [8j, 8j+8)
    const int i = tid >> 3;         // ray group: rays [8i, 8i+8)
    const int blockRay = blockIdx.x * RAYS_PB;

    const float iscx = s.isc[0], iscy = s.isc[1], iscz = s.isc[2];
    const float offx = s.off[0], offy = s.off[1], offz = s.off[2];
    const float hbc = s.bc, hbd = s.bd;

    float dist[8];
    #pragma unroll
    for (int rr = 0; rr < 8; ++rr) dist[rr] = INF_F;

    #pragma unroll 1
    for (int it = 0; it < T_ITERS; ++it) {
        __syncthreads();   // previous iter's GEMM reads of Xs complete

        // ---- build inputs: 1 ray/thread into Xs[d][ray] ----
        {
            const int lr = tid;
            const int gr = blockRay + lr;
            const float o0 = orig[3 * gr], o1 = orig[3 * gr + 1], o2 = orig[3 * gr + 2];
            const float v0 = vec[3 * gr],  v1 = vec[3 * gr + 1],  v2 = vec[3 * gr + 2];
            const float ct1 = t1[(size_t)it * N_RAYS + gr];
            const float ct2 = t2[(size_t)it * N_RAYS + gr];
            const float po0 = fmaf(v0, ct1, o0);
            const float po1 = fmaf(v1, ct1, o1);
            const float po2 = fmaf(v2, ct1, o2);
            const float dt = ct2 - ct1;
            const float pv0 = v0 * dt, pv1 = v1 * dt, pv2 = v2 * dt;
            #pragma unroll
            for (int k = 0; k < 8; ++k) {
                const float t = (float)k * (1.0f / 7.0f);
                s.Xs[3 * k + 0][lr] = fmaf(fmaf(pv0, t, po0), iscx, offx);
                s.Xs[3 * k + 1][lr] = fmaf(fmaf(pv1, t, po1), iscy, offy);
                s.Xs[3 * k + 2][lr] = fmaf(fmaf(pv2, t, po2), iscz, offz);
            }
        }
        __syncthreads();

        ull acc[8][4];

        #pragma unroll 1
        for (int L = 0; L < 3; ++L) {
            if (L == 0)      gemm_tile<IN_DIM>(&s.Xs[0][0], &s.W0[0][0],    s.b0,    i, j, acc);
            else if (L == 1) gemm_tile<DIM>   (&s.Xs[0][0], &s.Ws[0][0][0], s.bs[0], i, j, acc);
            else             gemm_tile<DIM>   (&s.Xs[0][0], &s.Ws[1][0][0], s.bs[1], i, j, acc);

            if (L == 2) break;

            // ---- relu + layernorm on the register tile (reduce over 8 j-threads) ----
            const ull* gu  = (const ull*)(s.g[L]  + 8 * j);
            const ull* beu = (const ull*)(s.be[L] + 8 * j);
            #pragma unroll
            for (int rr = 0; rr < 8; ++rr) {
                ull sp = pack2(0.f, 0.f);
                #pragma unroll
                for (int c = 0; c < 4; ++c) {
                    float lo, hi;
                    unpack2(acc[rr][c], lo, hi);
                    lo = fmaxf(lo, 0.f); hi = fmaxf(hi, 0.f);
                    acc[rr][c] = pack2(lo, hi);
                    sp = add2(sp, acc[rr][c]);
                }
                float sl, sh;
                unpack2(sp, sl, sh);
                float sum = sl + sh;
                sum += __shfl_xor_sync(0xFFFFFFFFu, sum, 1);
                sum += __shfl_xor_sync(0xFFFFFFFFu, sum, 2);
                sum += __shfl_xor_sync(0xFFFFFFFFu, sum, 4);
                const float mu = sum * (1.0f / DIM);
                const ull negmu = pack2(-mu, -mu);
                ull vp = pack2(0.f, 0.f);
                #pragma unroll
                for (int c = 0; c < 4; ++c) {
                    const ull d = add2(acc[rr][c], negmu);
                    fma2(vp, d, d);
                }
                float vl, vh;
                unpack2(vp, vl, vh);
                float var = vl + vh;
                var += __shfl_xor_sync(0xFFFFFFFFu, var, 1);
                var += __shfl_xor_sync(0xFFFFFFFFu, var, 2);
                var += __shfl_xor_sync(0xFFFFFFFFu, var, 4);
                const float rs = rsqrtf(var * (1.0f / DIM) + 1e-5f);
                const ull rs2 = pack2(rs, rs);
                #pragma unroll
                for (int c = 0; c < 4; ++c) {
                    const ull d  = add2(acc[rr][c], negmu);
                    const ull rg = mul2(gu[c], rs2);
                    acc[rr][c] = fma2v(d, rg, beu[c]);
                }
            }

            // ---- write back transposed: Xs[8j + col][rays] ----
            __syncthreads();
            #pragma unroll
            for (int c = 0; c < 4; ++c) {
                float fl[8], fh[8];
                #pragma unroll
                for (int rr = 0; rr < 8; ++rr) unpack2(acc[rr][c], fl[rr], fh[rr]);
                float* r0 = &s.Xs[8 * j + 2 * c][8 * i];
                float* r1 = &s.Xs[8 * j + 2 * c + 1][8 * i];
                *(float4*)(r0)     = make_float4(fl[0], fl[1], fl[2], fl[3]);
                *(float4*)(r0 + 4) = make_float4(fl[4], fl[5], fl[6], fl[7]);
                *(float4*)(r1)     = make_float4(fh[0], fh[1], fh[2], fh[3]);
                *(float4*)(r1 + 4) = make_float4(fh[4], fh[5], fh[6], fh[7]);
            }
            __syncthreads();
        }

        // ---- final relu + heads (partial over own 8 cols, butterfly over j) ----
        const ull* hwu = (const ull*)s.head + 8 * j;   // {Wc,Wd} per col
        const int gr8 = blockRay + 8 * i;
        const uint4 m0 = *(const uint4*)(masks + (size_t)it * N_RAYS + gr8);
        const uint4 m1 = *(const uint4*)(masks + (size_t)it * N_RAYS + gr8 + 4);
        const float4 t1a = *(const float4*)(t1 + (size_t)it * N_RAYS + gr8);
        const float4 t1b = *(const float4*)(t1 + (size_t)it * N_RAYS + gr8 + 4);
        const unsigned int mv[8] = { m0.x, m0.y, m0.z, m0.w, m1.x, m1.y, m1.z, m1.w };
        const float tv[8] = { t1a.x, t1a.y, t1a.z, t1a.w, t1b.x, t1b.y, t1b.z, t1b.w };

        #pragma unroll
        for (int rr = 0; rr < 8; ++rr) {
            ull h = pack2(0.f, 0.f);
            #pragma unroll
            for (int c = 0; c < 4; ++c) {
                float lo, hi;
                unpack2(acc[rr][c], lo, hi);
                lo = fmaxf(lo, 0.f); hi = fmaxf(hi, 0.f);
                fma2(h, pack2(lo, lo), hwu[2 * c]);
                fma2(h, pack2(hi, hi), hwu[2 * c + 1]);
            }
            h = add2(h, __shfl_xor_sync(0xFFFFFFFFu, h, 1));
            h = add2(h, __shfl_xor_sync(0xFFFFFFFFu, h, 2));
            h = add2(h, __shfl_xor_sync(0xFFFFFFFFu, h, 4));
            float cls, dvc;
            unpack2(h, cls, dvc);
            cls += hbc; dvc += hbd;
            if (mv[rr] != 0u && cls > 0.f) {
                const float dv = dvc + tv[rr];
                if (dv < dist[rr]) dist[rr] = dv;
            }
        }
    }

    // ---- output (j==0 threads own the rays) ----
    if (j == 0) {
        #pragma unroll
        for (int rr = 0; rr < 8; ++rr) {
            const int gr = blockRay + 8 * i + rr;
            float d = dist[rr];
            if (d == INF_F) d = 0.f;
            if (two_part) {
                out[gr]          = (d > 0.f) ? 1.f : 0.f;
                out[N_RAYS + gr] = d;
            } else {
                out[gr] = d;
            }
        }
    }
}

extern "C" void kernel_launch(void* const* d_in, const int* in_sizes, int n_in,
                              void* d_out, int out_size) {
    const float* orig      = (const float*)d_in[0];
    const float* vec       = (const float*)d_in[1];
    const unsigned int* masks = (const unsigned int*)d_in[2];
    /* d_in[3] = bbox_idxs (unused) */
    const float* t1        = (const float*)d_in[4];
    const float* t2        = (const float*)d_in[5];
    const float* mesh_min  = (const float*)d_in[6];
    const float* mesh_max  = (const float*)d_in[7];
    const float* W0        = (const float*)d_in[8];
    const float* b0        = (const float*)d_in[9];
    const float* ln_g      = (const float*)d_in[10];
    const float* ln_b      = (const float*)d_in[11];
    const float* Ws        = (const float*)d_in[12];
    const float* bs        = (const float*)d_in[13];
    const float* Wc        = (const float*)d_in[14];
    const float* bc        = (const float*)d_in[15];
    const float* Wd        = (const float*)d_in[16];
    const float* bd        = (const float*)d_in[17];

    const int two_part = (out_size >= 2 * N_RAYS) ? 1 : 0;
    const int smem = (int)sizeof(SM);

    cudaFuncSetAttribute(nbvh_kernel, cudaFuncAttributeMaxDynamicSharedMemorySize, smem);

    nbvh_kernel<<<N_RAYS / RAYS_PB, THREADS, smem>>>(
        orig, vec, masks, t1, t2, mesh_min, mesh_max,
        W0, b0, ln_g, ln_b, Ws, bs, Wc, bc, Wd, bd,
        (float*)d_out, two_part);
}

// round 12
// speedup vs baseline: 1.4018x; 1.4018x over previous
#include <cuda_runtime.h>

#define N_RAYS   (1 << 20)
#define T_ITERS  4
#define DIM      64
#define IN_DIM   24
#define INF_F    1e9f
#define XST      260          // Xs row stride in floats
#define RAYS_PB  256
#define THREADS  128

typedef unsigned long long ull;

__device__ __forceinline__ ull pack2(float lo, float hi) {
    ull r; asm("mov.b64 %0, {%1, %2};" : "=l"(r) : "f"(lo), "f"(hi)); return r;
}
__device__ __forceinline__ void unpack2(ull v, float& lo, float& hi) {
    asm("mov.b64 {%0, %1}, %2;" : "=f"(lo), "=f"(hi) : "l"(v));
}
__device__ __forceinline__ void fma2(ull& d, ull a, ull b) {
    asm("fma.rn.f32x2 %0, %1, %2, %0;" : "+l"(d) : "l"(a), "l"(b));
}
__device__ __forceinline__ ull fma2v(ull a, ull b, ull c) {
    ull r; asm("fma.rn.f32x2 %0, %1, %2, %3;" : "=l"(r) : "l"(a), "l"(b), "l"(c)); return r;
}
__device__ __forceinline__ ull add2(ull a, ull b) {
    ull r; asm("add.rn.f32x2 %0, %1, %2;" : "=l"(r) : "l"(a), "l"(b)); return r;
}
__device__ __forceinline__ ull mul2(ull a, ull b) {
    ull r; asm("mul.rn.f32x2 %0, %1, %2;" : "=l"(r) : "l"(a), "l"(b)); return r;
}

struct SM {
    float  W0[IN_DIM][DIM];   // 6 KB
    float  Ws[2][DIM][DIM];   // 32 KB
    float  b0[DIM];
    float  bs[2][DIM];
    float  g[2][DIM];
    float  be[2][DIM];
    float2 head[DIM];         // {Wc, Wd}
    float  isc[3], off[3], bc, bd;
    float  Xs[DIM][XST];      // transposed activations: [feature][slot]
    unsigned short sidx[RAYS_PB * T_ITERS];   // compacted tasks: it*256 + ray
    int    wcnt[4];
    int    ntask_s;
    float  sct1[RAYS_PB];     // per-pass ct1 per slot
    unsigned sdist[RAYS_PB];  // encoded min-dist per ray
};

// 8 slots x 16 cols tile
template<int K>
__device__ __forceinline__ void gemm_tile(const float* __restrict__ Xs,
                                          const float* __restrict__ W,
                                          const float* __restrict__ bias,
                                          int i, int j, ull (&acc)[8][8])
{
    const ull* bu = (const ull*)(bias + 16 * j);
    #pragma unroll
    for (int c = 0; c < 8; ++c) {
        const ull b2 = bu[c];
        #pragma unroll
        for (int rr = 0; rr < 8; ++rr) acc[rr][c] = b2;
    }
    const float* arow = Xs + 8 * i;
    const float* brow = W + 16 * j;
    #pragma unroll 4
    for (int k = 0; k < K; ++k) {
        const float4 a0 = *(const float4*)(arow);
        const float4 a1 = *(const float4*)(arow + 4);
        const ulonglong2 w0 = ((const ulonglong2*)brow)[0];
        const ulonglong2 w1 = ((const ulonglong2*)brow)[1];
        const ulonglong2 w2 = ((const ulonglong2*)brow)[2];
        const ulonglong2 w3 = ((const ulonglong2*)brow)[3];
        const ull b[8] = { w0.x, w0.y, w1.x, w1.y, w2.x, w2.y, w3.x, w3.y };
        const float av[8] = { a0.x, a0.y, a0.z, a0.w, a1.x, a1.y, a1.z, a1.w };
        #pragma unroll
        for (int rr = 0; rr < 8; ++rr) {
            const ull au = pack2(av[rr], av[rr]);
            #pragma unroll
            for (int c = 0; c < 8; ++c) fma2(acc[rr][c], au, b[c]);
        }
        arow += XST;
        brow += DIM;
    }
}

__global__ __launch_bounds__(THREADS) void nbvh_kernel(
    const float* __restrict__ orig, const float* __restrict__ vec,
    const unsigned int* __restrict__ masks,
    const float* __restrict__ t1, const float* __restrict__ t2,
    const float* __restrict__ mesh_min, const float* __restrict__ mesh_max,
    const float* __restrict__ W0, const float* __restrict__ b0,
    const float* __restrict__ ln_g, const float* __restrict__ ln_b,
    const float* __restrict__ Ws, const float* __restrict__ bs,
    const float* __restrict__ Wc, const float* __restrict__ bc,
    const float* __restrict__ Wd, const float* __restrict__ bd,
    float* __restrict__ out, int two_part)
{
    extern __shared__ SM sm[];
    SM& s = sm[0];
    const int tid  = threadIdx.x;
    const int lane = tid & 31;
    const int w    = tid >> 5;
    const int blockRay = blockIdx.x * RAYS_PB;

    // ---- weight staging ----
    for (int x = tid; x < IN_DIM * DIM; x += THREADS) ((float*)s.W0)[x] = W0[x];
    for (int x = tid; x < 2 * DIM * DIM; x += THREADS) ((float*)s.Ws)[x] = Ws[x];
    if (tid < DIM) {
        s.b0[tid]   = b0[tid];
        s.head[tid] = make_float2(Wc[tid], Wd[tid]);
    }
    for (int x = tid; x < 2 * DIM; x += THREADS) {
        ((float*)s.bs)[x] = bs[x];
        ((float*)s.g)[x]  = ln_g[x];
        ((float*)s.be)[x] = ln_b[x];
    }
    if (tid < 3) {
        float mn = mesh_min[tid], mx = mesh_max[tid];
        float min_infl = mn - 0.5f * (mx - mn);
        float is = 1.0f / (2.0f * (mx - mn));
        s.isc[tid] = is;
        s.off[tid] = -min_infl * is;
    }
    if (tid == 3) { s.bc = bc[0]; s.bd = bd[0]; }
    // init sdist (encoded: 0xFFFFFFFF > any encoding = "never updated")
    s.sdist[2 * tid]     = 0xFFFFFFFFu;
    s.sdist[2 * tid + 1] = 0xFFFFFFFFu;

    // ---- compaction: warp w handles iter w's 256 rays ----
    unsigned mbits = 0;
    #pragma unroll
    for (int q = 0; q < 8; ++q) {
        const int ray = q * 32 + lane;
        if (masks[(size_t)w * N_RAYS + blockRay + ray] != 0u) mbits |= 1u << q;
    }
    unsigned bq[8];
    int cnt = 0;
    #pragma unroll
    for (int q = 0; q < 8; ++q) {
        bq[q] = __ballot_sync(0xFFFFFFFFu, (mbits >> q) & 1u);
        cnt += __popc(bq[q]);
    }
    if (lane == 0) s.wcnt[w] = cnt;
    __syncthreads();
    if (tid == 0) {
        int acc0 = 0;
        #pragma unroll
        for (int ww = 0; ww < 4; ++ww) { const int c = s.wcnt[ww]; s.wcnt[ww] = acc0; acc0 += c; }
        s.ntask_s = acc0;
    }
    __syncthreads();
    {
        int run = s.wcnt[w];
        const unsigned lmask = (1u << lane) - 1u;
        #pragma unroll
        for (int q = 0; q < 8; ++q) {
            const unsigned b = bq[q];
            if ((mbits >> q) & 1u)
                s.sidx[run + __popc(b & lmask)] = (unsigned short)(w * 256 + q * 32 + lane);
            run += __popc(b);
        }
    }
    __syncthreads();

    const int ntask = s.ntask_s;
    const int npass = (ntask + RAYS_PB - 1) / RAYS_PB;

    const int j = tid & 3;          // col group: cols [16j, 16j+16)
    const int i = tid >> 2;         // slot group: slots [8i, 8i+8)
    const unsigned gmask = 0xFu << (lane & 28);   // 4-lane shuffle group (same i)

    const float iscx = s.isc[0], iscy = s.isc[1], iscz = s.isc[2];
    const float offx = s.off[0], offy = s.off[1], offz = s.off[2];
    const float hbc = s.bc, hbd = s.bd;

    #pragma unroll 1
    for (int p = 0; p < npass; ++p) {
        const int tb = p * RAYS_PB;
        const int ns = min(RAYS_PB, ntask - tb);

        __syncthreads();   // prior pass's GEMM reads of Xs / sct1 complete

        // ---- build inputs for slots [0, ns) ----
        for (int c = tid; c < ns; c += THREADS) {
            const int t  = s.sidx[tb + c];
            const int it = t >> 8;
            const int gr = blockRay + (t & 255);
            const float o0 = orig[3 * gr], o1 = orig[3 * gr + 1], o2 = orig[3 * gr + 2];
            const float v0 = vec[3 * gr],  v1 = vec[3 * gr + 1],  v2 = vec[3 * gr + 2];
            const float ct1 = t1[(size_t)it * N_RAYS + gr];
            const float ct2 = t2[(size_t)it * N_RAYS + gr];
            s.sct1[c] = ct1;
            const float po0 = fmaf(v0, ct1, o0);
            const float po1 = fmaf(v1, ct1, o1);
            const float po2 = fmaf(v2, ct1, o2);
            const float dt = ct2 - ct1;
            const float pv0 = v0 * dt, pv1 = v1 * dt, pv2 = v2 * dt;
            #pragma unroll
            for (int k = 0; k < 8; ++k) {
                const float t8 = (float)k * (1.0f / 7.0f);
                s.Xs[3 * k + 0][c] = fmaf(fmaf(pv0, t8, po0), iscx, offx);
                s.Xs[3 * k + 1][c] = fmaf(fmaf(pv1, t8, po1), iscy, offy);
                s.Xs[3 * k + 2][c] = fmaf(fmaf(pv2, t8, po2), iscz, offz);
            }
        }
        __syncthreads();

        const bool active = (8 * i < ns);
        ull acc[8][8];

        #pragma unroll 1
        for (int L = 0; L < 3; ++L) {
            if (active) {
                if (L == 0)      gemm_tile<IN_DIM>(&s.Xs[0][0], &s.W0[0][0],    s.b0,    i, j, acc);
                else if (L == 1) gemm_tile<DIM>   (&s.Xs[0][0], &s.Ws[0][0][0], s.bs[0], i, j, acc);
                else             gemm_tile<DIM>   (&s.Xs[0][0], &s.Ws[1][0][0], s.bs[1], i, j, acc);
            }
            if (L == 2) break;

            if (active) {
                // ---- relu + layernorm on register tile (reduce over 4 j-lanes) ----
                const ull* gu  = (const ull*)(s.g[L]  + 16 * j);
                const ull* beu = (const ull*)(s.be[L] + 16 * j);
                #pragma unroll
                for (int rr = 0; rr < 8; ++rr) {
                    ull sp = pack2(0.f, 0.f);
                    #pragma unroll
                    for (int c = 0; c < 8; ++c) {
                        float lo, hi;
                        unpack2(acc[rr][c], lo, hi);
                        lo = fmaxf(lo, 0.f); hi = fmaxf(hi, 0.f);
                        acc[rr][c] = pack2(lo, hi);
                        sp = add2(sp, acc[rr][c]);
                    }
                    float sl, sh;
                    unpack2(sp, sl, sh);
                    float sum = sl + sh;
                    sum += __shfl_xor_sync(gmask, sum, 1);
                    sum += __shfl_xor_sync(gmask, sum, 2);
                    const float mu = sum * (1.0f / DIM);
                    const ull negmu = pack2(-mu, -mu);
                    ull vp = pack2(0.f, 0.f);
                    #pragma unroll
                    for (int c = 0; c < 8; ++c) {
                        const ull d = add2(acc[rr][c], negmu);
                        fma2(vp, d, d);
                    }
                    float vl, vh;
                    unpack2(vp, vl, vh);
                    float var = vl + vh;
                    var += __shfl_xor_sync(gmask, var, 1);
                    var += __shfl_xor_sync(gmask, var, 2);
                    const float rs = rsqrtf(var * (1.0f / DIM) + 1e-5f);
                    const ull rs2 = pack2(rs, rs);
                    #pragma unroll
                    for (int c = 0; c < 8; ++c) {
                        const ull d  = add2(acc[rr][c], negmu);
                        const ull rg = mul2(gu[c], rs2);
                        acc[rr][c] = fma2v(d, rg, beu[c]);
                    }
                }
            }

            __syncthreads();
            if (active) {
                #pragma unroll
                for (int c = 0; c < 8; ++c) {
                    float fl[8], fh[8];
                    #pragma unroll
                    for (int rr = 0; rr < 8; ++rr) unpack2(acc[rr][c], fl[rr], fh[rr]);
                    float* r0 = &s.Xs[16 * j + 2 * c][8 * i];
                    float* r1 = &s.Xs[16 * j + 2 * c + 1][8 * i];
                    *(float4*)(r0)     = make_float4(fl[0], fl[1], fl[2], fl[3]);
                    *(float4*)(r0 + 4) = make_float4(fl[4], fl[5], fl[6], fl[7]);
                    *(float4*)(r1)     = make_float4(fh[0], fh[1], fh[2], fh[3]);
                    *(float4*)(r1 + 4) = make_float4(fh[4], fh[5], fh[6], fh[7]);
                }
            }
            __syncthreads();
        }

        // ---- final relu + heads + atomic min-update ----
        if (active) {
            const ull* hwu = (const ull*)s.head + 16 * j;
            #pragma unroll
            for (int rr = 0; rr < 8; ++rr) {
                ull h = pack2(0.f, 0.f);
                #pragma unroll
                for (int c = 0; c < 8; ++c) {
                    float lo, hi;
                    unpack2(acc[rr][c], lo, hi);
                    lo = fmaxf(lo, 0.f); hi = fmaxf(hi, 0.f);
                    fma2(h, pack2(lo, lo), hwu[2 * c]);
                    fma2(h, pack2(hi, hi), hwu[2 * c + 1]);
                }
                h = add2(h, __shfl_xor_sync(gmask, h, 1));
                h = add2(h, __shfl_xor_sync(gmask, h, 2));
                const int slot = 8 * i + rr;
                if (j == 0 && slot < ns) {
                    float cls, dvc;
                    unpack2(h, cls, dvc);
                    cls += hbc; dvc += hbd;
                    if (cls > 0.f) {
                        const float dv = dvc + s.sct1[slot];
                        const int ray = s.sidx[tb + slot] & 255;
                        unsigned ku = __float_as_uint(dv);
                        const unsigned enc = (ku & 0x80000000u) ? ~ku : (ku | 0x80000000u);
                        atomicMin(&s.sdist[ray], enc);
                    }
                }
            }
        }
    }

    __syncthreads();

    // ---- output: decode sdist (2 rays per thread) ----
    #pragma unroll
    for (int q = 0; q < 2; ++q) {
        const int ray = 2 * tid + q;
        const int gr = blockRay + ray;
        const unsigned v = s.sdist[ray];
        float d;
        if (v == 0xFFFFFFFFu) d = 0.f;
        else {
            const unsigned u = (v & 0x80000000u) ? (v ^ 0x80000000u) : ~v;
            d = __uint_as_float(u);
        }
        if (two_part) {
            out[gr]          = (d > 0.f) ? 1.f : 0.f;
            out[N_RAYS + gr] = d;
        } else {
            out[gr] = d;
        }
    }
}

extern "C" void kernel_launch(void* const* d_in, const int* in_sizes, int n_in,
                              void* d_out, int out_size) {
    const float* orig      = (const float*)d_in[0];
    const float* vec       = (const float*)d_in[1];
    const unsigned int* masks = (const unsigned int*)d_in[2];
    /* d_in[3] = bbox_idxs (unused) */
    const float* t1        = (const float*)d_in[4];
    const float* t2        = (const float*)d_in[5];
    const float* mesh_min  = (const float*)d_in[6];
    const float* mesh_max  = (const float*)d_in[7];
    const float* W0        = (const float*)d_in[8];
    const float* b0        = (const float*)d_in[9];
    const float* ln_g      = (const float*)d_in[10];
    const float* ln_b      = (const float*)d_in[11];
    const float* Ws        = (const float*)d_in[12];
    const float* bs        = (const float*)d_in[13];
    const float* Wc        = (const float*)d_in[14];
    const float* bc        = (const float*)d_in[15];
    const float* Wd        = (const float*)d_in[16];
    const float* bd        = (const float*)d_in[17];

    const int two_part = (out_size >= 2 * N_RAYS) ? 1 : 0;
    const int smem = (int)sizeof(SM);

    cudaFuncSetAttribute(nbvh_kernel, cudaFuncAttributeMaxDynamicSharedMemorySize, smem);

    nbvh_kernel<<<N_RAYS / RAYS_PB, THREADS, smem>>>(
        orig, vec, masks, t1, t2, mesh_min, mesh_max,
        W0, b0, ln_g, ln_b, Ws, bs, Wc, bc, Wd, bd,
        (float*)d_out, two_part);
}

// round 13
// speedup vs baseline: 1.6975x; 1.2109x over previous
#include <cuda_runtime.h>

#define N_RAYS   (1 << 20)
#define T_ITERS  4
#define DIM      64
#define IN_DIM   24
#define INF_F    1e9f
#define XST      260
#define SLOTS    256
#define THREADS  128
#define MAX_TASKS (T_ITERS * N_RAYS)
#define GEMM_BLOCKS (MAX_TASKS / SLOTS)

typedef unsigned long long ull;

// ---- device scratch (allocation-free rule: __device__ globals) ----
__device__ unsigned g_tasks[MAX_TASKS];   // (it << 20) | ray
__device__ unsigned g_dist[N_RAYS];       // monotonic-encoded min dist
__device__ int      g_ntask;

__device__ __forceinline__ ull pack2(float lo, float hi) {
    ull r; asm("mov.b64 %0, {%1, %2};" : "=l"(r) : "f"(lo), "f"(hi)); return r;
}
__device__ __forceinline__ void unpack2(ull v, float& lo, float& hi) {
    asm("mov.b64 {%0, %1}, %2;" : "=f"(lo), "=f"(hi) : "l"(v));
}
__device__ __forceinline__ void fma2(ull& d, ull a, ull b) {
    asm("fma.rn.f32x2 %0, %1, %2, %0;" : "+l"(d) : "l"(a), "l"(b));
}
__device__ __forceinline__ ull fma2v(ull a, ull b, ull c) {
    ull r; asm("fma.rn.f32x2 %0, %1, %2, %3;" : "=l"(r) : "l"(a), "l"(b), "l"(c)); return r;
}
__device__ __forceinline__ ull add2(ull a, ull b) {
    ull r; asm("add.rn.f32x2 %0, %1, %2;" : "=l"(r) : "l"(a), "l"(b)); return r;
}
__device__ __forceinline__ ull mul2(ull a, ull b) {
    ull r; asm("mul.rn.f32x2 %0, %1, %2;" : "=l"(r) : "l"(a), "l"(b)); return r;
}

struct SM {
    float  W0[IN_DIM][DIM];
    float  Ws[2][DIM][DIM];
    float  b0[DIM];
    float  bs[2][DIM];
    float  g[2][DIM];
    float  be[2][DIM];
    float2 head[DIM];
    float  isc[3], off[3], bc, bd;
    float  Xs[DIM][XST];
    unsigned stask[SLOTS];
    float  sct1[SLOTS];
};

// ================= kernel 1: reset =================
__global__ void reset_kernel() { if (threadIdx.x == 0) g_ntask = 0; }

// ================= kernel 2: compaction =================
__global__ __launch_bounds__(256) void compact_kernel(const unsigned* __restrict__ masks) {
    const int r = blockIdx.x * 256 + threadIdx.x;
    g_dist[r] = 0xFFFFFFFFu;
    unsigned tk[T_ITERS];
    int n = 0;
    #pragma unroll
    for (int it = 0; it < T_ITERS; ++it)
        if (masks[(size_t)it * N_RAYS + r] != 0u) tk[n++] = ((unsigned)it << 20) | (unsigned)r;

    const int lane = threadIdx.x & 31;
    int scan = n;                               // inclusive prefix within warp
    #pragma unroll
    for (int d = 1; d < 32; d <<= 1) {
        const int v = __shfl_up_sync(0xFFFFFFFFu, scan, d);
        if (lane >= d) scan += v;
    }
    const int wtotal = __shfl_sync(0xFFFFFFFFu, scan, 31);
    int base = 0;
    if (lane == 31) base = atomicAdd(&g_ntask, wtotal);
    base = __shfl_sync(0xFFFFFFFFu, base, 31);
    const int my = base + scan - n;
    for (int q = 0; q < n; ++q) g_tasks[my + q] = tk[q];
}

// ================= kernel 3: GEMM over compacted tasks =================
template<int K>
__device__ __forceinline__ void gemm_tile(const float* __restrict__ Xs,
                                          const float* __restrict__ W,
                                          const float* __restrict__ bias,
                                          int i, int j, ull (&acc)[8][8])
{
    const ull* bu = (const ull*)(bias + 16 * j);
    #pragma unroll
    for (int c = 0; c < 8; ++c) {
        const ull b2 = bu[c];
        #pragma unroll
        for (int rr = 0; rr < 8; ++rr) acc[rr][c] = b2;
    }
    const float* arow = Xs + 8 * i;
    const float* brow = W + 16 * j;
    #pragma unroll 4
    for (int k = 0; k < K; ++k) {
        const float4 a0 = *(const float4*)(arow);
        const float4 a1 = *(const float4*)(arow + 4);
        const ulonglong2 w0 = ((const ulonglong2*)brow)[0];
        const ulonglong2 w1 = ((const ulonglong2*)brow)[1];
        const ulonglong2 w2 = ((const ulonglong2*)brow)[2];
        const ulonglong2 w3 = ((const ulonglong2*)brow)[3];
        const ull b[8] = { w0.x, w0.y, w1.x, w1.y, w2.x, w2.y, w3.x, w3.y };
        const float av[8] = { a0.x, a0.y, a0.z, a0.w, a1.x, a1.y, a1.z, a1.w };
        #pragma unroll
        for (int rr = 0; rr < 8; ++rr) {
            const ull au = pack2(av[rr], av[rr]);
            #pragma unroll
            for (int c = 0; c < 8; ++c) fma2(acc[rr][c], au, b[c]);
        }
        arow += XST;
        brow += DIM;
    }
}

__global__ __launch_bounds__(THREADS) void nbvh_gemm_kernel(
    const float* __restrict__ orig, const float* __restrict__ vec,
    const float* __restrict__ t1, const float* __restrict__ t2,
    const float* __restrict__ mesh_min, const float* __restrict__ mesh_max,
    const float* __restrict__ W0, const float* __restrict__ b0,
    const float* __restrict__ ln_g, const float* __restrict__ ln_b,
    const float* __restrict__ Ws, const float* __restrict__ bs,
    const float* __restrict__ Wc, const float* __restrict__ bc,
    const float* __restrict__ Wd, const float* __restrict__ bd)
{
    const int ntask = g_ntask;
    const int tb = blockIdx.x * SLOTS;
    if (tb >= ntask) return;
    const int ns = min(SLOTS, ntask - tb);

    extern __shared__ SM sm[];
    SM& s = sm[0];
    const int tid  = threadIdx.x;
    const int lane = tid & 31;

    // ---- weight staging ----
    for (int x = tid; x < IN_DIM * DIM; x += THREADS) ((float*)s.W0)[x] = W0[x];
    for (int x = tid; x < 2 * DIM * DIM; x += THREADS) ((float*)s.Ws)[x] = Ws[x];
    if (tid < DIM) {
        s.b0[tid]   = b0[tid];
        s.head[tid] = make_float2(Wc[tid], Wd[tid]);
    }
    for (int x = tid; x < 2 * DIM; x += THREADS) {
        ((float*)s.bs)[x] = bs[x];
        ((float*)s.g)[x]  = ln_g[x];
        ((float*)s.be)[x] = ln_b[x];
    }
    if (tid < 3) {
        const float mn = mesh_min[tid], mx = mesh_max[tid];
        const float min_infl = mn - 0.5f * (mx - mn);
        const float is = 1.0f / (2.0f * (mx - mn));
        s.isc[tid] = is;
        s.off[tid] = -min_infl * is;
    }
    if (tid == 3) { s.bc = bc[0]; s.bd = bd[0]; }
    __syncthreads();

    const float iscx = s.isc[0], iscy = s.isc[1], iscz = s.isc[2];
    const float offx = s.off[0], offy = s.off[1], offz = s.off[2];
    const float hbc = s.bc, hbd = s.bd;

    // ---- build inputs for slots [0, ns) ----
    for (int c = tid; c < ns; c += THREADS) {
        const unsigned t = g_tasks[tb + c];
        const int it = (int)(t >> 20);
        const int gr = (int)(t & 0xFFFFFu);
        s.stask[c] = t;
        const float o0 = orig[3 * gr], o1 = orig[3 * gr + 1], o2 = orig[3 * gr + 2];
        const float v0 = vec[3 * gr],  v1 = vec[3 * gr + 1],  v2 = vec[3 * gr + 2];
        const float ct1 = t1[(size_t)it * N_RAYS + gr];
        const float ct2 = t2[(size_t)it * N_RAYS + gr];
        s.sct1[c] = ct1;
        const float po0 = fmaf(v0, ct1, o0);
        const float po1 = fmaf(v1, ct1, o1);
        const float po2 = fmaf(v2, ct1, o2);
        const float dt = ct2 - ct1;
        const float pv0 = v0 * dt, pv1 = v1 * dt, pv2 = v2 * dt;
        #pragma unroll
        for (int k = 0; k < 8; ++k) {
            const float t8 = (float)k * (1.0f / 7.0f);
            s.Xs[3 * k + 0][c] = fmaf(fmaf(pv0, t8, po0), iscx, offx);
            s.Xs[3 * k + 1][c] = fmaf(fmaf(pv1, t8, po1), iscy, offy);
            s.Xs[3 * k + 2][c] = fmaf(fmaf(pv2, t8, po2), iscz, offz);
        }
    }
    __syncthreads();

    const int j = tid & 3;
    const int i = tid >> 2;
    const unsigned gmask = 0xFu << (lane & 28);
    const bool active = (8 * i < ns);
    ull acc[8][8];

    #pragma unroll 1
    for (int L = 0; L < 3; ++L) {
        if (active) {
            if (L == 0)      gemm_tile<IN_DIM>(&s.Xs[0][0], &s.W0[0][0],    s.b0,    i, j, acc);
            else if (L == 1) gemm_tile<DIM>   (&s.Xs[0][0], &s.Ws[0][0][0], s.bs[0], i, j, acc);
            else             gemm_tile<DIM>   (&s.Xs[0][0], &s.Ws[1][0][0], s.bs[1], i, j, acc);
        }
        if (L == 2) break;

        if (active) {
            const ull* gu  = (const ull*)(s.g[L]  + 16 * j);
            const ull* beu = (const ull*)(s.be[L] + 16 * j);
            #pragma unroll
            for (int rr = 0; rr < 8; ++rr) {
                ull sp = pack2(0.f, 0.f);
                #pragma unroll
                for (int c = 0; c < 8; ++c) {
                    float lo, hi;
                    unpack2(acc[rr][c], lo, hi);
                    lo = fmaxf(lo, 0.f); hi = fmaxf(hi, 0.f);
                    acc[rr][c] = pack2(lo, hi);
                    sp = add2(sp, acc[rr][c]);
                }
                float sl, sh;
                unpack2(sp, sl, sh);
                float sum = sl + sh;
                sum += __shfl_xor_sync(gmask, sum, 1);
                sum += __shfl_xor_sync(gmask, sum, 2);
                const float mu = sum * (1.0f / DIM);
                const ull negmu = pack2(-mu, -mu);
                ull vp = pack2(0.f, 0.f);
                #pragma unroll
                for (int c = 0; c < 8; ++c) {
                    const ull d = add2(acc[rr][c], negmu);
                    fma2(vp, d, d);
                }
                float vl, vh;
                unpack2(vp, vl, vh);
                float var = vl + vh;
                var += __shfl_xor_sync(gmask, var, 1);
                var += __shfl_xor_sync(gmask, var, 2);
                const float rs = rsqrtf(var * (1.0f / DIM) + 1e-5f);
                const ull rs2 = pack2(rs, rs);
                #pragma unroll
                for (int c = 0; c < 8; ++c) {
                    const ull d  = add2(acc[rr][c], negmu);
                    const ull rg = mul2(gu[c], rs2);
                    acc[rr][c] = fma2v(d, rg, beu[c]);
                }
            }
        }

        __syncthreads();
        if (active) {
            #pragma unroll
            for (int c = 0; c < 8; ++c) {
                float fl[8], fh[8];
                #pragma unroll
                for (int rr = 0; rr < 8; ++rr) unpack2(acc[rr][c], fl[rr], fh[rr]);
                float* r0 = &s.Xs[16 * j + 2 * c][8 * i];
                float* r1 = &s.Xs[16 * j + 2 * c + 1][8 * i];
                *(float4*)(r0)     = make_float4(fl[0], fl[1], fl[2], fl[3]);
                *(float4*)(r0 + 4) = make_float4(fl[4], fl[5], fl[6], fl[7]);
                *(float4*)(r1)     = make_float4(fh[0], fh[1], fh[2], fh[3]);
                *(float4*)(r1 + 4) = make_float4(fh[4], fh[5], fh[6], fh[7]);
            }
        }
        __syncthreads();
    }

    // ---- final relu + heads + global atomic min-update ----
    if (active) {
        const ull* hwu = (const ull*)s.head + 16 * j;
        #pragma unroll
        for (int rr = 0; rr < 8; ++rr) {
            ull h = pack2(0.f, 0.f);
            #pragma unroll
            for (int c = 0; c < 8; ++c) {
                float lo, hi;
                unpack2(acc[rr][c], lo, hi);
                lo = fmaxf(lo, 0.f); hi = fmaxf(hi, 0.f);
                fma2(h, pack2(lo, lo), hwu[2 * c]);
                fma2(h, pack2(hi, hi), hwu[2 * c + 1]);
            }
            h = add2(h, __shfl_xor_sync(gmask, h, 1));
            h = add2(h, __shfl_xor_sync(gmask, h, 2));
            const int slot = 8 * i + rr;
            if (j == 0 && slot < ns) {
                float cls, dvc;
                unpack2(h, cls, dvc);
                cls += hbc; dvc += hbd;
                if (cls > 0.f) {
                    const float dv = dvc + s.sct1[slot];
                    const int ray = (int)(s.stask[slot] & 0xFFFFFu);
                    const unsigned ku = __float_as_uint(dv);
                    const unsigned enc = (ku & 0x80000000u) ? ~ku : (ku | 0x80000000u);
                    atomicMin(&g_dist[ray], enc);
                }
            }
        }
    }
}

// ================= kernel 4: output =================
__global__ __launch_bounds__(256) void output_kernel(float* __restrict__ out, int two_part) {
    const int r = blockIdx.x * 256 + threadIdx.x;
    const unsigned v = g_dist[r];
    float d;
    if (v == 0xFFFFFFFFu) d = 0.f;
    else {
        const unsigned u = (v & 0x80000000u) ? (v ^ 0x80000000u) : ~v;
        d = __uint_as_float(u);
        if (d == INF_F) d = 0.f;
    }
    if (two_part) {
        out[r]          = (d > 0.f) ? 1.f : 0.f;
        out[N_RAYS + r] = d;
    } else {
        out[r] = d;
    }
}

extern "C" void kernel_launch(void* const* d_in, const int* in_sizes, int n_in,
                              void* d_out, int out_size) {
    const float* orig      = (const float*)d_in[0];
    const float* vec       = (const float*)d_in[1];
    const unsigned int* masks = (const unsigned int*)d_in[2];
    /* d_in[3] = bbox_idxs (unused) */
    const float* t1        = (const float*)d_in[4];
    const float* t2        = (const float*)d_in[5];
    const float* mesh_min  = (const float*)d_in[6];
    const float* mesh_max  = (const float*)d_in[7];
    const float* W0        = (const float*)d_in[8];
    const float* b0        = (const float*)d_in[9];
    const float* ln_g      = (const float*)d_in[10];
    const float* ln_b      = (const float*)d_in[11];
    const float* Ws        = (const float*)d_in[12];
    const float* bs        = (const float*)d_in[13];
    const float* Wc        = (const float*)d_in[14];
    const float* bc        = (const float*)d_in[15];
    const float* Wd        = (const float*)d_in[16];
    const float* bd        = (const float*)d_in[17];

    const int two_part = (out_size >= 2 * N_RAYS) ? 1 : 0;
    const int smem = (int)sizeof(SM);

    cudaFuncSetAttribute(nbvh_gemm_kernel, cudaFuncAttributeMaxDynamicSharedMemorySize, smem);

    reset_kernel<<<1, 32>>>();
    compact_kernel<<<N_RAYS / 256, 256>>>(masks);
    nbvh_gemm_kernel<<<GEMM_BLOCKS, THREADS, smem>>>(
        orig, vec, t1, t2, mesh_min, mesh_max,
        W0, b0, ln_g, ln_b, Ws, bs, Wc, bc, Wd, bd);
    output_kernel<<<N_RAYS / 256, 256>>>((float*)d_out, two_part);
}

// round 15
// speedup vs baseline: 1.7720x; 1.0439x over previous
#include <cuda_runtime.h>

#define N_RAYS   (1 << 20)
#define T_ITERS  4
#define DIM      64
#define IN_DIM   24
#define INF_F    1e9f
#define XST      260
#define SLOTS    256
#define THREADS  128
#define MAX_TASKS (T_ITERS * N_RAYS)
#define GRID_GEMM 1480

typedef unsigned long long ull;

// ---- device scratch ----
__device__ unsigned g_tasks[MAX_TASKS];   // (it << 20) | ray
__device__ unsigned g_dist[N_RAYS];       // monotonic-encoded min dist
__device__ int      g_ntask;

__device__ __forceinline__ ull pack2(float lo, float hi) {
    ull r; asm("mov.b64 %0, {%1, %2};" : "=l"(r) : "f"(lo), "f"(hi)); return r;
}
__device__ __forceinline__ void unpack2(ull v, float& lo, float& hi) {
    asm("mov.b64 {%0, %1}, %2;" : "=f"(lo), "=f"(hi) : "l"(v));
}
__device__ __forceinline__ void fma2(ull& d, ull a, ull b) {
    asm("fma.rn.f32x2 %0, %1, %2, %0;" : "+l"(d) : "l"(a), "l"(b));
}
__device__ __forceinline__ ull fma2v(ull a, ull b, ull c) {
    ull r; asm("fma.rn.f32x2 %0, %1, %2, %3;" : "=l"(r) : "l"(a), "l"(b), "l"(c)); return r;
}
__device__ __forceinline__ ull add2(ull a, ull b) {
    ull r; asm("add.rn.f32x2 %0, %1, %2;" : "=l"(r) : "l"(a), "l"(b)); return r;
}
__device__ __forceinline__ ull mul2(ull a, ull b) {
    ull r; asm("mul.rn.f32x2 %0, %1, %2;" : "=l"(r) : "l"(a), "l"(b)); return r;
}

struct SM {
    float  W0[IN_DIM][DIM];   // permuted rows
    float  Ws[2][DIM][DIM];   // permuted rows
    float  b0[DIM];
    float  bs[2][DIM];
    float  g[2][DIM];
    float  be[2][DIM];
    float2 head[DIM];
    float  isc[3], off[3], bc, bd;
    float  Xs[DIM][XST];
    unsigned stask[SLOTS];
    float  sct1[SLOTS];
};

// ================= kernel 1: reset =================
__global__ void reset_kernel() { if (threadIdx.x == 0) g_ntask = 0; }

// ================= kernel 2: compaction =================
__global__ __launch_bounds__(256) void compact_kernel(const unsigned* __restrict__ masks) {
    const int r = blockIdx.x * 256 + threadIdx.x;
    g_dist[r] = 0xFFFFFFFFu;
    unsigned tk[T_ITERS];
    int n = 0;
    #pragma unroll
    for (int it = 0; it < T_ITERS; ++it)
        if (masks[(size_t)it * N_RAYS + r] != 0u) tk[n++] = ((unsigned)it << 20) | (unsigned)r;

    const int lane = threadIdx.x & 31;
    int scan = n;
    #pragma unroll
    for (int d = 1; d < 32; d <<= 1) {
        const int v = __shfl_up_sync(0xFFFFFFFFu, scan, d);
        if (lane >= d) scan += v;
    }
    const int wtotal = __shfl_sync(0xFFFFFFFFu, scan, 31);
    int base = 0;
    if (lane == 31) base = atomicAdd(&g_ntask, wtotal);
    base = __shfl_sync(0xFFFFFFFFu, base, 31);
    const int my = base + scan - n;
    for (int q = 0; q < n; ++q) g_tasks[my + q] = tk[q];
}

// ================= kernel 3: persistent GEMM =================
// Weight rows permuted: logical col n -> phys = q*16 + j*4 + e, with j=n>>4, q=(n>>2)&3, e=n&3.
// Load q (16B at brow + q*16 floats, brow offset 4j) yields logical cols 16j+4q..+3 => acc c=2q,2q+1.
template<int K>
__device__ __forceinline__ void gemm_tile(const float* __restrict__ Xs,
                                          const float* __restrict__ W,
                                          const float* __restrict__ bias,
                                          int i, int j, ull (&acc)[8][8])
{
    const ull* bu = (const ull*)(bias + 16 * j);
    #pragma unroll
    for (int c = 0; c < 8; ++c) {
        const ull b2 = bu[c];
        #pragma unroll
        for (int rr = 0; rr < 8; ++rr) acc[rr][c] = b2;
    }
    const float* arow = Xs + 8 * i;
    const float* brow = W + 4 * j;
    #pragma unroll 4
    for (int k = 0; k < K; ++k) {
        const float4 a0 = *(const float4*)(arow);
        const float4 a1 = *(const float4*)(arow + 4);
        const ulonglong2 w0 = *(const ulonglong2*)(brow);        // conflict-free: 4j*4B stride
        const ulonglong2 w1 = *(const ulonglong2*)(brow + 16);
        const ulonglong2 w2 = *(const ulonglong2*)(brow + 32);
        const ulonglong2 w3 = *(const ulonglong2*)(brow + 48);
        const ull b[8] = { w0.x, w0.y, w1.x, w1.y, w2.x, w2.y, w3.x, w3.y };
        const float av[8] = { a0.x, a0.y, a0.z, a0.w, a1.x, a1.y, a1.z, a1.w };
        #pragma unroll
        for (int rr = 0; rr < 8; ++rr) {
            const ull au = pack2(av[rr], av[rr]);
            #pragma unroll
            for (int c = 0; c < 8; ++c) fma2(acc[rr][c], au, b[c]);
        }
        arow += XST;
        brow += DIM;
    }
}

__global__ __launch_bounds__(THREADS) void nbvh_gemm_kernel(
    const float* __restrict__ orig, const float* __restrict__ vec,
    const float* __restrict__ t1, const float* __restrict__ t2,
    const float* __restrict__ mesh_min, const float* __restrict__ mesh_max,
    const float* __restrict__ W0, const float* __restrict__ b0,
    const float* __restrict__ ln_g, const float* __restrict__ ln_b,
    const float* __restrict__ Ws, const float* __restrict__ bs,
    const float* __restrict__ Wc, const float* __restrict__ bc,
    const float* __restrict__ Wd, const float* __restrict__ bd)
{
    extern __shared__ SM sm[];
    SM& s = sm[0];
    const int tid  = threadIdx.x;
    const int lane = tid & 31;

    // ---- weight staging (once per block), permuted layout ----
    for (int idx = tid; idx < IN_DIM * DIM; idx += THREADS) {
        const int k = idx >> 6, n = idx & 63;
        const int jj = n >> 4, q = (n >> 2) & 3, e = n & 3;
        s.W0[k][q * 16 + jj * 4 + e] = W0[idx];
    }
    for (int idx = tid; idx < 2 * DIM * DIM; idx += THREADS) {
        const int L = idx >> 12, rem = idx & 4095;
        const int k = rem >> 6, n = rem & 63;
        const int jj = n >> 4, q = (n >> 2) & 3, e = n & 3;
        s.Ws[L][k][q * 16 + jj * 4 + e] = Ws[idx];
    }
    if (tid < DIM) {
        s.b0[tid]   = b0[tid];
        s.head[tid] = make_float2(Wc[tid], Wd[tid]);
    }
    for (int x = tid; x < 2 * DIM; x += THREADS) {
        ((float*)s.bs)[x] = bs[x];
        ((float*)s.g)[x]  = ln_g[x];
        ((float*)s.be)[x] = ln_b[x];
    }
    if (tid < 3) {
        const float mn = mesh_min[tid], mx = mesh_max[tid];
        const float min_infl = mn - 0.5f * (mx - mn);
        const float is = 1.0f / (2.0f * (mx - mn));
        s.isc[tid] = is;
        s.off[tid] = -min_infl * is;
    }
    if (tid == 3) { s.bc = bc[0]; s.bd = bd[0]; }
    __syncthreads();

    const float iscx = s.isc[0], iscy = s.isc[1], iscz = s.isc[2];
    const float offx = s.off[0], offy = s.off[1], offz = s.off[2];
    const float hbc = s.bc, hbd = s.bd;

    const int ntask  = g_ntask;
    const int nbatch = (ntask + SLOTS - 1) / SLOTS;

    const int j = tid & 3;
    const int i = tid >> 2;
    const unsigned gmask = 0xFu << (lane & 28);

    #pragma unroll 1
    for (int bt = blockIdx.x; bt < nbatch; bt += GRID_GEMM) {
        const int tb = bt * SLOTS;
        const int ns = min(SLOTS, ntask - tb);

        __syncthreads();   // previous batch's reads of Xs/sct1/stask complete

        // ---- build inputs for slots [0, ns) ----
        for (int c = tid; c < ns; c += THREADS) {
            const unsigned t = g_tasks[tb + c];
            const int it = (int)(t >> 20);
            const int gr = (int)(t & 0xFFFFFu);
            s.stask[c] = t;
            const float o0 = orig[3 * gr], o1 = orig[3 * gr + 1], o2 = orig[3 * gr + 2];
            const float v0 = vec[3 * gr],  v1 = vec[3 * gr + 1],  v2 = vec[3 * gr + 2];
            const float ct1 = t1[(size_t)it * N_RAYS + gr];
            const float ct2 = t2[(size_t)it * N_RAYS + gr];
            s.sct1[c] = ct1;
            const float po0 = fmaf(v0, ct1, o0);
            const float po1 = fmaf(v1, ct1, o1);
            const float po2 = fmaf(v2, ct1, o2);
            const float dt = ct2 - ct1;
            const float pv0 = v0 * dt, pv1 = v1 * dt, pv2 = v2 * dt;
            #pragma unroll
            for (int k = 0; k < 8; ++k) {
                const float t8 = (float)k * (1.0f / 7.0f);
                s.Xs[3 * k + 0][c] = fmaf(fmaf(pv0, t8, po0), iscx, offx);
                s.Xs[3 * k + 1][c] = fmaf(fmaf(pv1, t8, po1), iscy, offy);
                s.Xs[3 * k + 2][c] = fmaf(fmaf(pv2, t8, po2), iscz, offz);
            }
        }
        __syncthreads();

        const bool active = (8 * i < ns);
        ull acc[8][8];

        #pragma unroll 1
        for (int L = 0; L < 3; ++L) {
            if (active) {
                if (L == 0)      gemm_tile<IN_DIM>(&s.Xs[0][0], &s.W0[0][0],    s.b0,    i, j, acc);
                else if (L == 1) gemm_tile<DIM>   (&s.Xs[0][0], &s.Ws[0][0][0], s.bs[0], i, j, acc);
                else             gemm_tile<DIM>   (&s.Xs[0][0], &s.Ws[1][0][0], s.bs[1], i, j, acc);
            }
            if (L == 2) break;

            if (active) {
                // ---- relu + single-pass stats + layernorm ----
                const ull* gu  = (const ull*)(s.g[L]  + 16 * j);
                const ull* beu = (const ull*)(s.be[L] + 16 * j);
                #pragma unroll
                for (int rr = 0; rr < 8; ++rr) {
                    ull sp = pack2(0.f, 0.f);
                    ull qp = pack2(0.f, 0.f);
                    #pragma unroll
                    for (int c = 0; c < 8; ++c) {
                        float lo, hi;
                        unpack2(acc[rr][c], lo, hi);
                        lo = fmaxf(lo, 0.f); hi = fmaxf(hi, 0.f);
                        acc[rr][c] = pack2(lo, hi);
                        sp = add2(sp, acc[rr][c]);
                        fma2(qp, acc[rr][c], acc[rr][c]);
                    }
                    float sl, sh, ql, qh;
                    unpack2(sp, sl, sh);
                    unpack2(qp, ql, qh);
                    float sum = sl + sh;
                    float ssq = ql + qh;
                    sum += __shfl_xor_sync(gmask, sum, 1);
                    ssq += __shfl_xor_sync(gmask, ssq, 1);
                    sum += __shfl_xor_sync(gmask, sum, 2);
                    ssq += __shfl_xor_sync(gmask, ssq, 2);
                    const float mu  = sum * (1.0f / DIM);
                    const float var = fmaxf(fmaf(-mu, mu, ssq * (1.0f / DIM)), 0.f);
                    const float rs  = rsqrtf(var + 1e-5f);
                    const ull negmu = pack2(-mu, -mu);
                    const ull rs2   = pack2(rs, rs);
                    #pragma unroll
                    for (int c = 0; c < 8; ++c) {
                        const ull d  = add2(acc[rr][c], negmu);
                        const ull rg = mul2(gu[c], rs2);
                        acc[rr][c] = fma2v(d, rg, beu[c]);
                    }
                }
            }

            __syncthreads();
            if (active) {
                #pragma unroll
                for (int c = 0; c < 8; ++c) {
                    float fl[8], fh[8];
                    #pragma unroll
                    for (int rr = 0; rr < 8; ++rr) unpack2(acc[rr][c], fl[rr], fh[rr]);
                    float* r0 = &s.Xs[16 * j + 2 * c][8 * i];
                    float* r1 = &s.Xs[16 * j + 2 * c + 1][8 * i];
                    *(float4*)(r0)     = make_float4(fl[0], fl[1], fl[2], fl[3]);
                    *(float4*)(r0 + 4) = make_float4(fl[4], fl[5], fl[6], fl[7]);
                    *(float4*)(r1)     = make_float4(fh[0], fh[1], fh[2], fh[3]);
                    *(float4*)(r1 + 4) = make_float4(fh[4], fh[5], fh[6], fh[7]);
                }
            }
            __syncthreads();
        }

        // ---- final relu + heads + global atomic min-update ----
        if (active) {
            const ull* hwu = (const ull*)s.head + 16 * j;
            #pragma unroll
            for (int rr = 0; rr < 8; ++rr) {
                ull h = pack2(0.f, 0.f);
                #pragma unroll
                for (int c = 0; c < 8; ++c) {
                    float lo, hi;
                    unpack2(acc[rr][c], lo, hi);
                    lo = fmaxf(lo, 0.f); hi = fmaxf(hi, 0.f);
                    fma2(h, pack2(lo, lo), hwu[2 * c]);
                    fma2(h, pack2(hi, hi), hwu[2 * c + 1]);
                }
                h = add2(h, __shfl_xor_sync(gmask, h, 1));
                h = add2(h, __shfl_xor_sync(gmask, h, 2));
                const int slot = 8 * i + rr;
                if (j == 0 && slot < ns) {
                    float cls, dvc;
                    unpack2(h, cls, dvc);
                    cls += hbc; dvc += hbd;
                    if (cls > 0.f) {
                        const float dv = dvc + s.sct1[slot];
                        const int ray = (int)(s.stask[slot] & 0xFFFFFu);
                        const unsigned ku = __float_as_uint(dv);
                        const unsigned enc = (ku & 0x80000000u) ? ~ku : (ku | 0x80000000u);
                        atomicMin(&g_dist[ray], enc);
                    }
                }
            }
        }
    }
}

// ================= kernel 4: output =================
__global__ __launch_bounds__(256) void output_kernel(float* __restrict__ out, int two_part) {
    const int r = blockIdx.x * 256 + threadIdx.x;
    const unsigned v = g_dist[r];
    float d;
    if (v == 0xFFFFFFFFu) d = 0.f;
    else {
        const unsigned u = (v & 0x80000000u) ? (v ^ 0x80000000u) : ~v;
        d = __uint_as_float(u);
        if (d == INF_F) d = 0.f;
    }
    if (two_part) {
        out[r]          = (d > 0.f) ? 1.f : 0.f;
        out[N_RAYS + r] = d;
    } else {
        out[r] = d;
    }
}

extern "C" void kernel_launch(void* const* d_in, const int* in_sizes, int n_in,
                              void* d_out, int out_size) {
    const float* orig      = (const float*)d_in[0];
    const float* vec       = (const float*)d_in[1];
    const unsigned int* masks = (const unsigned int*)d_in[2];
    /* d_in[3] = bbox_idxs (unused) */
    const float* t1        = (const float*)d_in[4];
    const float* t2        = (const float*)d_in[5];
    const float* mesh_min  = (const float*)d_in[6];
    const float* mesh_max  = (const float*)d_in[7];
    const float* W0        = (const float*)d_in[8];
    const float* b0        = (const float*)d_in[9];
    const float* ln_g      = (const float*)d_in[10];
    const float* ln_b      = (const float*)d_in[11];
    const float* Ws        = (const float*)d_in[12];
    const float* bs        = (const float*)d_in[13];
    const float* Wc        = (const float*)d_in[14];
    const float* bc        = (const float*)d_in[15];
    const float* Wd        = (const float*)d_in[16];
    const float* bd        = (const float*)d_in[17];

    const int two_part = (out_size >= 2 * N_RAYS) ? 1 : 0;
    const int smem = (int)sizeof(SM);

    cudaFuncSetAttribute(nbvh_gemm_kernel, cudaFuncAttributeMaxDynamicSharedMemorySize, smem);

    reset_kernel<<<1, 32>>>();
    compact_kernel<<<N_RAYS / 256, 256>>>(masks);
    nbvh_gemm_kernel<<<GRID_GEMM, THREADS, smem>>>(
        orig, vec, t1, t2, mesh_min, mesh_max,
        W0, b0, ln_g, ln_b, Ws, bs, Wc, bc, Wd, bd);
    output_kernel<<<N_RAYS / 256, 256>>>((float*)d_out, two_part);
}

// round 16
// speedup vs baseline: 1.9406x; 1.0952x over previous
#include <cuda_runtime.h>

#define N_RAYS   (1 << 20)
#define T_ITERS  4
#define DIM      64
#define INF_F    1e9f
#define XST      260
#define SLOTS    256
#define THREADS  128
#define MAX_TASKS (T_ITERS * N_RAYS)
#define GRID_GEMM 1480

typedef unsigned long long ull;

// ---- device scratch ----
__device__ unsigned g_tasks[MAX_TASKS];   // (it << 20) | ray
__device__ unsigned g_dist[N_RAYS];       // monotonic-encoded min dist
__device__ int      g_ntask;

__device__ __forceinline__ ull pack2(float lo, float hi) {
    ull r; asm("mov.b64 %0, {%1, %2};" : "=l"(r) : "f"(lo), "f"(hi)); return r;
}
__device__ __forceinline__ void unpack2(ull v, float& lo, float& hi) {
    asm("mov.b64 {%0, %1}, %2;" : "=f"(lo), "=f"(hi) : "l"(v));
}
__device__ __forceinline__ void fma2(ull& d, ull a, ull b) {
    asm("fma.rn.f32x2 %0, %1, %2, %0;" : "+l"(d) : "l"(a), "l"(b));
}
__device__ __forceinline__ ull fma2v(ull a, ull b, ull c) {
    ull r; asm("fma.rn.f32x2 %0, %1, %2, %3;" : "=l"(r) : "l"(a), "l"(b), "l"(c)); return r;
}
__device__ __forceinline__ ull add2(ull a, ull b) {
    ull r; asm("add.rn.f32x2 %0, %1, %2;" : "=l"(r) : "l"(a), "l"(b)); return r;
}
__device__ __forceinline__ ull mul2(ull a, ull b) {
    ull r; asm("mul.rn.f32x2 %0, %1, %2;" : "=l"(r) : "l"(a), "l"(b)); return r;
}

struct SM {
    float  W0f[6][DIM];       // folded layer-0 weights, permuted rows
    float  Ws[2][DIM][DIM];   // permuted rows
    float  b0[DIM];
    float  bs[2][DIM];
    float  g[2][DIM];
    float  be[2][DIM];
    float2 head[DIM];
    float  isc[3], off[3], bc, bd;
    float  Xs[DIM][XST];
    unsigned stask[SLOTS];
    float  sct1[SLOTS];
};

// ================= kernel 1: reset =================
__global__ void reset_kernel() { if (threadIdx.x == 0) g_ntask = 0; }

// ================= kernel 2: compaction =================
__global__ __launch_bounds__(256) void compact_kernel(const unsigned* __restrict__ masks) {
    const int r = blockIdx.x * 256 + threadIdx.x;
    g_dist[r] = 0xFFFFFFFFu;
    unsigned tk[T_ITERS];
    int n = 0;
    #pragma unroll
    for (int it = 0; it < T_ITERS; ++it)
        if (masks[(size_t)it * N_RAYS + r] != 0u) tk[n++] = ((unsigned)it << 20) | (unsigned)r;

    const int lane = threadIdx.x & 31;
    int scan = n;
    #pragma unroll
    for (int d = 1; d < 32; d <<= 1) {
        const int v = __shfl_up_sync(0xFFFFFFFFu, scan, d);
        if (lane >= d) scan += v;
    }
    const int wtotal = __shfl_sync(0xFFFFFFFFu, scan, 31);
    int base = 0;
    if (lane == 31) base = atomicAdd(&g_ntask, wtotal);
    base = __shfl_sync(0xFFFFFFFFu, base, 31);
    const int my = base + scan - n;
    for (int q = 0; q < n; ++q) g_tasks[my + q] = tk[q];
}

// ================= kernel 3: persistent GEMM =================
// Weight rows permuted: logical col n -> phys = q*16 + j*4 + e (j=n>>4, q=(n>>2)&3, e=n&3).
template<int K>
__device__ __forceinline__ void gemm_tile(const float* __restrict__ Xs,
                                          const float* __restrict__ W,
                                          const float* __restrict__ bias,
                                          int i, int j, ull (&acc)[8][8])
{
    const ull* bu = (const ull*)(bias + 16 * j);
    #pragma unroll
    for (int c = 0; c < 8; ++c) {
        const ull b2 = bu[c];
        #pragma unroll
        for (int rr = 0; rr < 8; ++rr) acc[rr][c] = b2;
    }
    const float* arow = Xs + 8 * i;
    const float* brow = W + 4 * j;
    #pragma unroll 4
    for (int k = 0; k < K; ++k) {
        const float4 a0 = *(const float4*)(arow);
        const float4 a1 = *(const float4*)(arow + 4);
        const ulonglong2 w0 = *(const ulonglong2*)(brow);        // conflict-free
        const ulonglong2 w1 = *(const ulonglong2*)(brow + 16);
        const ulonglong2 w2 = *(const ulonglong2*)(brow + 32);
        const ulonglong2 w3 = *(const ulonglong2*)(brow + 48);
        const ull b[8] = { w0.x, w0.y, w1.x, w1.y, w2.x, w2.y, w3.x, w3.y };
        const float av[8] = { a0.x, a0.y, a0.z, a0.w, a1.x, a1.y, a1.z, a1.w };
        #pragma unroll
        for (int rr = 0; rr < 8; ++rr) {
            const ull au = pack2(av[rr], av[rr]);
            #pragma unroll
            for (int c = 0; c < 8; ++c) fma2(acc[rr][c], au, b[c]);
        }
        arow += XST;
        brow += DIM;
    }
}

__global__ __launch_bounds__(THREADS) void nbvh_gemm_kernel(
    const float* __restrict__ orig, const float* __restrict__ vec,
    const float* __restrict__ t1, const float* __restrict__ t2,
    const float* __restrict__ mesh_min, const float* __restrict__ mesh_max,
    const float* __restrict__ W0, const float* __restrict__ b0,
    const float* __restrict__ ln_g, const float* __restrict__ ln_b,
    const float* __restrict__ Ws, const float* __restrict__ bs,
    const float* __restrict__ Wc, const float* __restrict__ bc,
    const float* __restrict__ Wd, const float* __restrict__ bd)
{
    extern __shared__ SM sm[];
    SM& s = sm[0];
    const int tid  = threadIdx.x;
    const int lane = tid & 31;

    // ---- weight staging (once per block) ----
    // Fold layer 0 over the 8 sample points: x[3k+c] = A_c + t_k*B_c  =>
    //   W0f[c][n]   = sum_k W0[3k+c][n]
    //   W0f[3+c][n] = sum_k t_k * W0[3k+c][n]
    for (int idx = tid; idx < 6 * DIM; idx += THREADS) {
        const int c = idx >> 6, n = idx & 63;   // c in 0..5
        const int cc = (c < 3) ? c : c - 3;
        float acc0 = 0.f;
        if (c < 3) {
            #pragma unroll
            for (int k = 0; k < 8; ++k) acc0 += W0[(3 * k + cc) * DIM + n];
        } else {
            #pragma unroll
            for (int k = 0; k < 8; ++k) acc0 = fmaf((float)k * (1.0f / 7.0f), W0[(3 * k + cc) * DIM + n], acc0);
        }
        const int jj = n >> 4, q = (n >> 2) & 3, e = n & 3;
        s.W0f[c][q * 16 + jj * 4 + e] = acc0;
    }
    for (int idx = tid; idx < 2 * DIM * DIM; idx += THREADS) {
        const int L = idx >> 12, rem = idx & 4095;
        const int k = rem >> 6, n = rem & 63;
        const int jj = n >> 4, q = (n >> 2) & 3, e = n & 3;
        s.Ws[L][k][q * 16 + jj * 4 + e] = Ws[idx];
    }
    if (tid < DIM) {
        s.b0[tid]   = b0[tid];
        s.head[tid] = make_float2(Wc[tid], Wd[tid]);
    }
    for (int x = tid; x < 2 * DIM; x += THREADS) {
        ((float*)s.bs)[x] = bs[x];
        ((float*)s.g)[x]  = ln_g[x];
        ((float*)s.be)[x] = ln_b[x];
    }
    if (tid < 3) {
        const float mn = mesh_min[tid], mx = mesh_max[tid];
        const float min_infl = mn - 0.5f * (mx - mn);
        const float is = 1.0f / (2.0f * (mx - mn));
        s.isc[tid] = is;
        s.off[tid] = -min_infl * is;
    }
    if (tid == 3) { s.bc = bc[0]; s.bd = bd[0]; }
    __syncthreads();

    const float iscx = s.isc[0], iscy = s.isc[1], iscz = s.isc[2];
    const float offx = s.off[0], offy = s.off[1], offz = s.off[2];
    const float hbc = s.bc, hbd = s.bd;

    const int ntask  = g_ntask;
    const int nbatch = (ntask + SLOTS - 1) / SLOTS;

    const int j = tid & 3;
    const int i = tid >> 2;
    const unsigned gmask = 0xFu << (lane & 28);

    #pragma unroll 1
    for (int bt = blockIdx.x; bt < nbatch; bt += GRID_GEMM) {
        const int tb = bt * SLOTS;
        const int ns = min(SLOTS, ntask - tb);

        __syncthreads();   // previous batch's reads of Xs/sct1/stask complete

        // ---- build folded inputs: rows 0..2 = A_c, rows 3..5 = B_c ----
        for (int c = tid; c < ns; c += THREADS) {
            const unsigned t = g_tasks[tb + c];
            const int it = (int)(t >> 20);
            const int gr = (int)(t & 0xFFFFFu);
            s.stask[c] = t;
            const float o0 = orig[3 * gr], o1 = orig[3 * gr + 1], o2 = orig[3 * gr + 2];
            const float v0 = vec[3 * gr],  v1 = vec[3 * gr + 1],  v2 = vec[3 * gr + 2];
            const float ct1 = t1[(size_t)it * N_RAYS + gr];
            const float ct2 = t2[(size_t)it * N_RAYS + gr];
            s.sct1[c] = ct1;
            const float dt = ct2 - ct1;
            s.Xs[0][c] = fmaf(fmaf(v0, ct1, o0), iscx, offx);   // A_x
            s.Xs[1][c] = fmaf(fmaf(v1, ct1, o1), iscy, offy);   // A_y
            s.Xs[2][c] = fmaf(fmaf(v2, ct1, o2), iscz, offz);   // A_z
            s.Xs[3][c] = v0 * dt * iscx;                         // B_x
            s.Xs[4][c] = v1 * dt * iscy;                         // B_y
            s.Xs[5][c] = v2 * dt * iscz;                         // B_z
        }
        __syncthreads();

        const bool active = (8 * i < ns);
        ull acc[8][8];

        #pragma unroll 1
        for (int L = 0; L < 3; ++L) {
            if (active) {
                if (L == 0)      gemm_tile<6>  (&s.Xs[0][0], &s.W0f[0][0],   s.b0,    i, j, acc);
                else if (L == 1) gemm_tile<DIM>(&s.Xs[0][0], &s.Ws[0][0][0], s.bs[0], i, j, acc);
                else             gemm_tile<DIM>(&s.Xs[0][0], &s.Ws[1][0][0], s.bs[1], i, j, acc);
            }
            if (L == 2) break;

            if (active) {
                // ---- relu + single-pass stats + layernorm ----
                const ull* gu  = (const ull*)(s.g[L]  + 16 * j);
                const ull* beu = (const ull*)(s.be[L] + 16 * j);
                #pragma unroll
                for (int rr = 0; rr < 8; ++rr) {
                    ull sp = pack2(0.f, 0.f);
                    ull qp = pack2(0.f, 0.f);
                    #pragma unroll
                    for (int c = 0; c < 8; ++c) {
                        float lo, hi;
                        unpack2(acc[rr][c], lo, hi);
                        lo = fmaxf(lo, 0.f); hi = fmaxf(hi, 0.f);
                        acc[rr][c] = pack2(lo, hi);
                        sp = add2(sp, acc[rr][c]);
                        fma2(qp, acc[rr][c], acc[rr][c]);
                    }
                    float sl, sh, ql, qh;
                    unpack2(sp, sl, sh);
                    unpack2(qp, ql, qh);
                    float sum = sl + sh;
                    float ssq = ql + qh;
                    sum += __shfl_xor_sync(gmask, sum, 1);
                    ssq += __shfl_xor_sync(gmask, ssq, 1);
                    sum += __shfl_xor_sync(gmask, sum, 2);
                    ssq += __shfl_xor_sync(gmask, ssq, 2);
                    const float mu  = sum * (1.0f / DIM);
                    const float var = fmaxf(fmaf(-mu, mu, ssq * (1.0f / DIM)), 0.f);
                    const float rs  = rsqrtf(var + 1e-5f);
                    const ull negmu = pack2(-mu, -mu);
                    const ull rs2   = pack2(rs, rs);
                    #pragma unroll
                    for (int c = 0; c < 8; ++c) {
                        const ull d  = add2(acc[rr][c], negmu);
                        const ull rg = mul2(gu[c], rs2);
                        acc[rr][c] = fma2v(d, rg, beu[c]);
                    }
                }
            }

            __syncthreads();
            if (active) {
                #pragma unroll
                for (int c = 0; c < 8; ++c) {
                    float fl[8], fh[8];
                    #pragma unroll
                    for (int rr = 0; rr < 8; ++rr) unpack2(acc[rr][c], fl[rr], fh[rr]);
                    float* r0 = &s.Xs[16 * j + 2 * c][8 * i];
                    float* r1 = &s.Xs[16 * j + 2 * c + 1][8 * i];
                    *(float4*)(r0)     = make_float4(fl[0], fl[1], fl[2], fl[3]);
                    *(float4*)(r0 + 4) = make_float4(fl[4], fl[5], fl[6], fl[7]);
                    *(float4*)(r1)     = make_float4(fh[0], fh[1], fh[2], fh[3]);
                    *(float4*)(r1 + 4) = make_float4(fh[4], fh[5], fh[6], fh[7]);
                }
            }
            __syncthreads();
        }

        // ---- final relu + heads + global atomic min-update ----
        if (active) {
            const ull* hwu = (const ull*)s.head + 16 * j;
            #pragma unroll
            for (int rr = 0; rr < 8; ++rr) {
                ull h = pack2(0.f, 0.f);
                #pragma unroll
                for (int c = 0; c < 8; ++c) {
                    float lo, hi;
                    unpack2(acc[rr][c], lo, hi);
                    lo = fmaxf(lo, 0.f); hi = fmaxf(hi, 0.f);
                    fma2(h, pack2(lo, lo), hwu[2 * c]);
                    fma2(h, pack2(hi, hi), hwu[2 * c + 1]);
                }
                h = add2(h, __shfl_xor_sync(gmask, h, 1));
                h = add2(h, __shfl_xor_sync(gmask, h, 2));
                const int slot = 8 * i + rr;
                if (j == 0 && slot < ns) {
                    float cls, dvc;
                    unpack2(h, cls, dvc);
                    cls += hbc; dvc += hbd;
                    if (cls > 0.f) {
                        const float dv = dvc + s.sct1[slot];
                        const int ray = (int)(s.stask[slot] & 0xFFFFFu);
                        const unsigned ku = __float_as_uint(dv);
                        const unsigned enc = (ku & 0x80000000u) ? ~ku : (ku | 0x80000000u);
                        atomicMin(&g_dist[ray], enc);
                    }
                }
            }
        }
    }
}

// ================= kernel 4: output =================
__global__ __launch_bounds__(256) void output_kernel(float* __restrict__ out, int two_part) {
    const int r = blockIdx.x * 256 + threadIdx.x;
    const unsigned v = g_dist[r];
    float d;
    if (v == 0xFFFFFFFFu) d = 0.f;
    else {
        const unsigned u = (v & 0x80000000u) ? (v ^ 0x80000000u) : ~v;
        d = __uint_as_float(u);
        if (d == INF_F) d = 0.f;
    }
    if (two_part) {
        out[r]          = (d > 0.f) ? 1.f : 0.f;
        out[N_RAYS + r] = d;
    } else {
        out[r] = d;
    }
}

extern "C" void kernel_launch(void* const* d_in, const int* in_sizes, int n_in,
                              void* d_out, int out_size) {
    const float* orig      = (const float*)d_in[0];
    const float* vec       = (const float*)d_in[1];
    const unsigned int* masks = (const unsigned int*)d_in[2];
    /* d_in[3] = bbox_idxs (unused) */
    const float* t1        = (const float*)d_in[4];
    const float* t2        = (const float*)d_in[5];
    const float* mesh_min  = (const float*)d_in[6];
    const float* mesh_max  = (const float*)d_in[7];
    const float* W0        = (const float*)d_in[8];
    const float* b0        = (const float*)d_in[9];
    const float* ln_g      = (const float*)d_in[10];
    const float* ln_b      = (const float*)d_in[11];
    const float* Ws        = (const float*)d_in[12];
    const float* bs        = (const float*)d_in[13];
    const float* Wc        = (const float*)d_in[14];
    const float* bc        = (const float*)d_in[15];
    const float* Wd        = (const float*)d_in[16];
    const float* bd        = (const float*)d_in[17];

    const int two_part = (out_size >= 2 * N_RAYS) ? 1 : 0;
    const int smem = (int)sizeof(SM);

    cudaFuncSetAttribute(nbvh_gemm_kernel, cudaFuncAttributeMaxDynamicSharedMemorySize, smem);

    reset_kernel<<<1, 32>>>();
    compact_kernel<<<N_RAYS / 256, 256>>>(masks);
    nbvh_gemm_kernel<<<GRID_GEMM, THREADS, smem>>>(
        orig, vec, t1, t2, mesh_min, mesh_max,
        W0, b0, ln_g, ln_b, Ws, bs, Wc, bc, Wd, bd);
    output_kernel<<<N_RAYS / 256, 256>>>((float*)d_out, two_part);
}

// round 17
// speedup vs baseline: 1.9515x; 1.0056x over previous
#include <cuda_runtime.h>

#define N_RAYS   (1 << 20)
#define T_ITERS  4
#define DIM      64
#define INF_F    1e9f
#define XST      260
#define SLOTS    256
#define THREADS  128
#define MAX_TASKS (T_ITERS * N_RAYS)
#define GRID_GEMM 296

typedef unsigned long long ull;

// ---- device scratch ----
__device__ unsigned g_tasks[MAX_TASKS];   // (it << 20) | ray
__device__ unsigned g_dist[N_RAYS];       // monotonic-encoded min dist
__device__ int      g_ntask;
__device__ int      g_batch;              // dynamic work-stealing counter

__device__ __forceinline__ ull pack2(float lo, float hi) {
    ull r; asm("mov.b64 %0, {%1, %2};" : "=l"(r) : "f"(lo), "f"(hi)); return r;
}
__device__ __forceinline__ void unpack2(ull v, float& lo, float& hi) {
    asm("mov.b64 {%0, %1}, %2;" : "=f"(lo), "=f"(hi) : "l"(v));
}
__device__ __forceinline__ void fma2(ull& d, ull a, ull b) {
    asm("fma.rn.f32x2 %0, %1, %2, %0;" : "+l"(d) : "l"(a), "l"(b));
}
__device__ __forceinline__ ull fma2v(ull a, ull b, ull c) {
    ull r; asm("fma.rn.f32x2 %0, %1, %2, %3;" : "=l"(r) : "l"(a), "l"(b), "l"(c)); return r;
}
__device__ __forceinline__ ull add2(ull a, ull b) {
    ull r; asm("add.rn.f32x2 %0, %1, %2;" : "=l"(r) : "l"(a), "l"(b)); return r;
}
__device__ __forceinline__ ull mul2(ull a, ull b) {
    ull r; asm("mul.rn.f32x2 %0, %1, %2;" : "=l"(r) : "l"(a), "l"(b)); return r;
}

struct SM {
    float  W0f[6][DIM];       // folded layer-0 weights, permuted rows
    float  Ws[2][DIM][DIM];   // permuted rows
    float  b0[DIM];
    float  bs[2][DIM];
    float  g[2][DIM];
    float  be[2][DIM];
    float2 head[DIM];
    float  isc[3], off[3], bc, bd;
    float  Xs[DIM][XST];
    unsigned stask[SLOTS];
    float  sct1[SLOTS];
    int    next_bt;
};

// ================= kernel 1: reset =================
__global__ void reset_kernel() {
    if (threadIdx.x == 0) { g_ntask = 0; g_batch = 0; }
}

// ================= kernel 2: compaction =================
__global__ __launch_bounds__(256) void compact_kernel(const unsigned* __restrict__ masks) {
    const int r = blockIdx.x * 256 + threadIdx.x;
    g_dist[r] = 0xFFFFFFFFu;
    unsigned tk[T_ITERS];
    int n = 0;
    #pragma unroll
    for (int it = 0; it < T_ITERS; ++it)
        if (masks[(size_t)it * N_RAYS + r] != 0u) tk[n++] = ((unsigned)it << 20) | (unsigned)r;

    const int lane = threadIdx.x & 31;
    int scan = n;
    #pragma unroll
    for (int d = 1; d < 32; d <<= 1) {
        const int v = __shfl_up_sync(0xFFFFFFFFu, scan, d);
        if (lane >= d) scan += v;
    }
    const int wtotal = __shfl_sync(0xFFFFFFFFu, scan, 31);
    int base = 0;
    if (lane == 31) base = atomicAdd(&g_ntask, wtotal);
    base = __shfl_sync(0xFFFFFFFFu, base, 31);
    const int my = base + scan - n;
    for (int q = 0; q < n; ++q) g_tasks[my + q] = tk[q];
}

// ================= kernel 3: persistent GEMM =================
// Weight rows permuted: logical col n -> phys = q*16 + j*4 + e (j=n>>4, q=(n>>2)&3, e=n&3).
template<int K>
__device__ __forceinline__ void gemm_tile(const float* __restrict__ Xs,
                                          const float* __restrict__ W,
                                          const float* __restrict__ bias,
                                          int i, int j, ull (&acc)[8][8])
{
    const ull* bu = (const ull*)(bias + 16 * j);
    #pragma unroll
    for (int c = 0; c < 8; ++c) {
        const ull b2 = bu[c];
        #pragma unroll
        for (int rr = 0; rr < 8; ++rr) acc[rr][c] = b2;
    }
    const float* arow = Xs + 8 * i;
    const float* brow = W + 4 * j;
    #pragma unroll 4
    for (int k = 0; k < K; ++k) {
        const float4 a0 = *(const float4*)(arow);
        const float4 a1 = *(const float4*)(arow + 4);
        const ulonglong2 w0 = *(const ulonglong2*)(brow);        // conflict-free
        const ulonglong2 w1 = *(const ulonglong2*)(brow + 16);
        const ulonglong2 w2 = *(const ulonglong2*)(brow + 32);
        const ulonglong2 w3 = *(const ulonglong2*)(brow + 48);
        const ull b[8] = { w0.x, w0.y, w1.x, w1.y, w2.x, w2.y, w3.x, w3.y };
        const float av[8] = { a0.x, a0.y, a0.z, a0.w, a1.x, a1.y, a1.z, a1.w };
        #pragma unroll
        for (int rr = 0; rr < 8; ++rr) {
            const ull au = pack2(av[rr], av[rr]);
            #pragma unroll
            for (int c = 0; c < 8; ++c) fma2(acc[rr][c], au, b[c]);
        }
        arow += XST;
        brow += DIM;
    }
}

__global__ __launch_bounds__(THREADS) void nbvh_gemm_kernel(
    const float* __restrict__ orig, const float* __restrict__ vec,
    const float* __restrict__ t1, const float* __restrict__ t2,
    const float* __restrict__ mesh_min, const float* __restrict__ mesh_max,
    const float* __restrict__ W0, const float* __restrict__ b0,
    const float* __restrict__ ln_g, const float* __restrict__ ln_b,
    const float* __restrict__ Ws, const float* __restrict__ bs,
    const float* __restrict__ Wc, const float* __restrict__ bc,
    const float* __restrict__ Wd, const float* __restrict__ bd)
{
    extern __shared__ SM sm[];
    SM& s = sm[0];
    const int tid  = threadIdx.x;
    const int lane = tid & 31;

    // ---- weight staging (once per block) ----
    // Fold layer 0 over the 8 sample points: x[3k+c] = A_c + t_k*B_c  =>
    //   W0f[c][n]   = sum_k W0[3k+c][n]
    //   W0f[3+c][n] = sum_k t_k * W0[3k+c][n]
    for (int idx = tid; idx < 6 * DIM; idx += THREADS) {
        const int c = idx >> 6, n = idx & 63;   // c in 0..5
        const int cc = (c < 3) ? c : c - 3;
        float acc0 = 0.f;
        if (c < 3) {
            #pragma unroll
            for (int k = 0; k < 8; ++k) acc0 += W0[(3 * k + cc) * DIM + n];
        } else {
            #pragma unroll
            for (int k = 0; k < 8; ++k) acc0 = fmaf((float)k * (1.0f / 7.0f), W0[(3 * k + cc) * DIM + n], acc0);
        }
        const int jj = n >> 4, q = (n >> 2) & 3, e = n & 3;
        s.W0f[c][q * 16 + jj * 4 + e] = acc0;
    }
    for (int idx = tid; idx < 2 * DIM * DIM; idx += THREADS) {
        const int L = idx >> 12, rem = idx & 4095;
        const int k = rem >> 6, n = rem & 63;
        const int jj = n >> 4, q = (n >> 2) & 3, e = n & 3;
        s.Ws[L][k][q * 16 + jj * 4 + e] = Ws[idx];
    }
    if (tid < DIM) {
        s.b0[tid]   = b0[tid];
        s.head[tid] = make_float2(Wc[tid], Wd[tid]);
    }
    for (int x = tid; x < 2 * DIM; x += THREADS) {
        ((float*)s.bs)[x] = bs[x];
        ((float*)s.g)[x]  = ln_g[x];
        ((float*)s.be)[x] = ln_b[x];
    }
    if (tid < 3) {
        const float mn = mesh_min[tid], mx = mesh_max[tid];
        const float min_infl = mn - 0.5f * (mx - mn);
        const float is = 1.0f / (2.0f * (mx - mn));
        s.isc[tid] = is;
        s.off[tid] = -min_infl * is;
    }
    if (tid == 3) { s.bc = bc[0]; s.bd = bd[0]; }

    const int ntask  = g_ntask;
    const int nbatch = (ntask + SLOTS - 1) / SLOTS;

    const float iscx = mesh_min ? 0.f : 0.f;  // (placeholder removed below)
    (void)iscx;

    if (tid == 0) s.next_bt = atomicAdd(&g_batch, 1);
    __syncthreads();

    const float isx = s.isc[0], isy = s.isc[1], isz = s.isc[2];
    const float ofx = s.off[0], ofy = s.off[1], ofz = s.off[2];
    const float hbc = s.bc, hbd = s.bd;

    const int j = tid & 3;
    const int i = tid >> 2;
    const unsigned gmask = 0xFu << (lane & 28);

    #pragma unroll 1
    for (;;) {
        const int bt = s.next_bt;
        if (bt >= nbatch) break;
        const int tb = bt * SLOTS;
        const int ns = min(SLOTS, ntask - tb);

        // ---- build folded inputs: rows 0..2 = A_c, rows 3..5 = B_c ----
        for (int c = tid; c < ns; c += THREADS) {
            const unsigned t = g_tasks[tb + c];
            const int it = (int)(t >> 20);
            const int gr = (int)(t & 0xFFFFFu);
            s.stask[c] = t;
            const float o0 = orig[3 * gr], o1 = orig[3 * gr + 1], o2 = orig[3 * gr + 2];
            const float v0 = vec[3 * gr],  v1 = vec[3 * gr + 1],  v2 = vec[3 * gr + 2];
            const float ct1 = t1[(size_t)it * N_RAYS + gr];
            const float ct2 = t2[(size_t)it * N_RAYS + gr];
            s.sct1[c] = ct1;
            const float dt = ct2 - ct1;
            s.Xs[0][c] = fmaf(fmaf(v0, ct1, o0), isx, ofx);   // A_x
            s.Xs[1][c] = fmaf(fmaf(v1, ct1, o1), isy, ofy);   // A_y
            s.Xs[2][c] = fmaf(fmaf(v2, ct1, o2), isz, ofz);   // A_z
            s.Xs[3][c] = v0 * dt * isx;                        // B_x
            s.Xs[4][c] = v1 * dt * isy;                        // B_y
            s.Xs[5][c] = v2 * dt * isz;                        // B_z
        }
        __syncthreads();

        const bool active = (8 * i < ns);
        ull acc[8][8];

        #pragma unroll 1
        for (int L = 0; L < 3; ++L) {
            if (active) {
                if (L == 0)      gemm_tile<6>  (&s.Xs[0][0], &s.W0f[0][0],   s.b0,    i, j, acc);
                else if (L == 1) gemm_tile<DIM>(&s.Xs[0][0], &s.Ws[0][0][0], s.bs[0], i, j, acc);
                else             gemm_tile<DIM>(&s.Xs[0][0], &s.Ws[1][0][0], s.bs[1], i, j, acc);
            }
            if (L == 2) break;

            if (active) {
                // ---- relu + single-pass stats + layernorm ----
                const ull* gu  = (const ull*)(s.g[L]  + 16 * j);
                const ull* beu = (const ull*)(s.be[L] + 16 * j);
                #pragma unroll
                for (int rr = 0; rr < 8; ++rr) {
                    ull sp = pack2(0.f, 0.f);
                    ull qp = pack2(0.f, 0.f);
                    #pragma unroll
                    for (int c = 0; c < 8; ++c) {
                        float lo, hi;
                        unpack2(acc[rr][c], lo, hi);
                        lo = fmaxf(lo, 0.f); hi = fmaxf(hi, 0.f);
                        acc[rr][c] = pack2(lo, hi);
                        sp = add2(sp, acc[rr][c]);
                        fma2(qp, acc[rr][c], acc[rr][c]);
                    }
                    float sl, sh, ql, qh;
                    unpack2(sp, sl, sh);
                    unpack2(qp, ql, qh);
                    float sum = sl + sh;
                    float ssq = ql + qh;
                    sum += __shfl_xor_sync(gmask, sum, 1);
                    ssq += __shfl_xor_sync(gmask, ssq, 1);
                    sum += __shfl_xor_sync(gmask, sum, 2);
                    ssq += __shfl_xor_sync(gmask, ssq, 2);
                    const float mu  = sum * (1.0f / DIM);
                    const float var = fmaxf(fmaf(-mu, mu, ssq * (1.0f / DIM)), 0.f);
                    const float rs  = rsqrtf(var + 1e-5f);
                    const ull negmu = pack2(-mu, -mu);
                    const ull rs2   = pack2(rs, rs);
                    #pragma unroll
                    for (int c = 0; c < 8; ++c) {
                        const ull d  = add2(acc[rr][c], negmu);
                        const ull rg = mul2(gu[c], rs2);
                        acc[rr][c] = fma2v(d, rg, beu[c]);
                    }
                }
            }

            __syncthreads();
            if (active) {
                #pragma unroll
                for (int c = 0; c < 8; ++c) {
                    float fl[8], fh[8];
                    #pragma unroll
                    for (int rr = 0; rr < 8; ++rr) unpack2(acc[rr][c], fl[rr], fh[rr]);
                    float* r0 = &s.Xs[16 * j + 2 * c][8 * i];
                    float* r1 = &s.Xs[16 * j + 2 * c + 1][8 * i];
                    *(float4*)(r0)     = make_float4(fl[0], fl[1], fl[2], fl[3]);
                    *(float4*)(r0 + 4) = make_float4(fl[4], fl[5], fl[6], fl[7]);
                    *(float4*)(r1)     = make_float4(fh[0], fh[1], fh[2], fh[3]);
                    *(float4*)(r1 + 4) = make_float4(fh[4], fh[5], fh[6], fh[7]);
                }
            }
            __syncthreads();
        }

        // ---- final relu + heads + global atomic min-update ----
        if (active) {
            const ull* hwu = (const ull*)s.head + 16 * j;
            #pragma unroll
            for (int rr = 0; rr < 8; ++rr) {
                ull h = pack2(0.f, 0.f);
                #pragma unroll
                for (int c = 0; c < 8; ++c) {
                    float lo, hi;
                    unpack2(acc[rr][c], lo, hi);
                    lo = fmaxf(lo, 0.f); hi = fmaxf(hi, 0.f);
                    fma2(h, pack2(lo, lo), hwu[2 * c]);
                    fma2(h, pack2(hi, hi), hwu[2 * c + 1]);
                }
                h = add2(h, __shfl_xor_sync(gmask, h, 1));
                h = add2(h, __shfl_xor_sync(gmask, h, 2));
                const int slot = 8 * i + rr;
                if (j == 0 && slot < ns) {
                    float cls, dvc;
                    unpack2(h, cls, dvc);
                    cls += hbc; dvc += hbd;
                    if (cls > 0.f) {
                        const float dv = dvc + s.sct1[slot];
                        const int ray = (int)(s.stask[slot] & 0xFFFFFu);
                        const unsigned ku = __float_as_uint(dv);
                        const unsigned enc = (ku & 0x80000000u) ? ~ku : (ku | 0x80000000u);
                        atomicMin(&g_dist[ray], enc);
                    }
                }
            }
        }

        // ---- fetch next batch (reuses the barrier needed before Xs overwrite) ----
        __syncthreads();
        if (tid == 0) s.next_bt = atomicAdd(&g_batch, 1);
        __syncthreads();
    }
}

// ================= kernel 4: output =================
__global__ __launch_bounds__(256) void output_kernel(float* __restrict__ out, int two_part) {
    const int r = blockIdx.x * 256 + threadIdx.x;
    const unsigned v = g_dist[r];
    float d;
    if (v == 0xFFFFFFFFu) d = 0.f;
    else {
        const unsigned u = (v & 0x80000000u) ? (v ^ 0x80000000u) : ~v;
        d = __uint_as_float(u);
        if (d == INF_F) d = 0.f;
    }
    if (two_part) {
        out[r]          = (d > 0.f) ? 1.f : 0.f;
        out[N_RAYS + r] = d;
    } else {
        out[r] = d;
    }
}

extern "C" void kernel_launch(void* const* d_in, const int* in_sizes, int n_in,
                              void* d_out, int out_size) {
    const float* orig      = (const float*)d_in[0];
    const float* vec       = (const float*)d_in[1];
    const unsigned int* masks = (const unsigned int*)d_in[2];
    /* d_in[3] = bbox_idxs (unused) */
    const float* t1        = (const float*)d_in[4];
    const float* t2        = (const float*)d_in[5];
    const float* mesh_min  = (const float*)d_in[6];
    const float* mesh_max  = (const float*)d_in[7];
    const float* W0        = (const float*)d_in[8];
    const float* b0        = (const float*)d_in[9];
    const float* ln_g      = (const float*)d_in[10];
    const float* ln_b      = (const float*)d_in[11];
    const float* Ws        = (const float*)d_in[12];
    const float* bs        = (const float*)d_in[13];
    const float* Wc        = (const float*)d_in[14];
    const float* bc        = (const float*)d_in[15];
    const float* Wd        = (const float*)d_in[16];
    const float* bd        = (const float*)d_in[17];

    const int two_part = (out_size >= 2 * N_RAYS) ? 1 : 0;
    const int smem = (int)sizeof(SM);

    cudaFuncSetAttribute(nbvh_gemm_kernel, cudaFuncAttributeMaxDynamicSharedMemorySize, smem);

    reset_kernel<<<1, 32>>>();
    compact_kernel<<<N_RAYS / 256, 256>>>(masks);
    nbvh_gemm_kernel<<<GRID_GEMM, THREADS, smem>>>(
        orig, vec, t1, t2, mesh_min, mesh_max,
        W0, b0, ln_g, ln_b, Ws, bs, Wc, bc, Wd, bd);
    output_kernel<<<N_RAYS / 256, 256>>>((float*)d_out, two_part);
}